// round 13
// baseline (speedup 1.0000x reference)
#include <cuda_runtime.h>
#include <math.h>

#define NBLK 128
#define NTHR 512
#define ALPHA 0.2f
#define NE 819

// SMEM float offsets: per-layer weights [k][8] (ff rows then Dale-signed rec rows)
#define WOFF0 0          // 1536*8
#define WOFF1 12288      // 2048*8
#define WOFF2 28672      // 2048*8
#define REDO  45056      // 16 x 32 x 8 reduction (per batch-group)
#define HBUF  49152      // 32*9
#define OBUF  49440      // 32*9
#define SMEM_BYTES (49728 * 4)

#define AH_OFF 8388608
#define AH_L   8454144
#define BH     65536

__device__ float g_xT[128 * 512 * 64];
__device__ float g_h[2][3][1024 * 64];
__device__ float g_ci[2][2][1024 * 64];
__device__ int g_cnt16[16];     // rotating (phase, group) arrival counters
__device__ int g_init;

__global__ void xt_kernel(const float* __restrict__ x) {
    int idx = blockIdx.x * 256 + threadIdx.x;
    int b = idx & 63, k = (idx >> 6) & 511, t = idx >> 15;
    g_xT[idx] = x[t * 32768 + b * 512 + k];
    if (idx < 16) g_cnt16[idx] = 0;
    if (idx == 16) g_init = 0;
}

__device__ __forceinline__ void wait_ge(const int* p, int val) {
    int v;
    do {
        asm volatile("ld.global.cg.b32 %0, [%1];" : "=r"(v) : "l"(p));
        if (v >= val) break;
        __nanosleep(64);
    } while (true);
    __threadfence();
}

__device__ void load_w(const float* __restrict__ g, int K, float* dst, int dale, int tid) {
    for (int idx = tid; idx < 8 * K; idx += NTHR) {
        int i = idx / K, k = idx - i * K;
        float v = fabsf(g[i * K + k]);
        if (dale && k >= NE) v = -v;
        dst[k * 8 + i] = v;
    }
}

#define FMA2(A, W, X) asm("fma.rn.f32x2 %0, %1, %2, %0;" : "+l"(A) : "l"(W), "l"(X))
#define ADD2(A, B)    asm("add.rn.f32x2 %0, %0, %1;" : "+l"(A) : "l"(B))

// 8 cols x 2 batches (one batch-group) per thread; slice covers k = kb + 32*i.
// Depth-8 rotating prefetch hides L2 latency.
template <int N>
__device__ __forceinline__ void accum(unsigned long long acc[4][2],
                                      const float* __restrict__ act,
                                      const float* __restrict__ wsm,
                                      int kb, int goff, int b2) {
    const float2* ap = (const float2*)(act + kb * 64 + goff + b2);
    const ulonglong2* wp = (const ulonglong2*)(wsm + kb * 8);
    float2 abuf[8];
#pragma unroll
    for (int j = 0; j < 8; j++) abuf[j] = __ldcg(ap + j * 1024);
#pragma unroll
    for (int i = 0; i < N; i++) {
        float2 a = abuf[i & 7];
        if (i + 8 < N) abuf[i & 7] = __ldcg(ap + (i + 8) * 1024);
        ulonglong2 w01 = wp[i * 64];
        ulonglong2 w23 = wp[i * 64 + 1];
        unsigned long long ab0, ab1;
        asm("mov.b64 %0, {%1, %1};" : "=l"(ab0) : "f"(a.x));
        asm("mov.b64 %0, {%1, %1};" : "=l"(ab1) : "f"(a.y));
        FMA2(acc[0][0], w01.x, ab0);
        FMA2(acc[1][0], w01.y, ab0);
        FMA2(acc[2][0], w23.x, ab0);
        FMA2(acc[3][0], w23.y, ab0);
        FMA2(acc[0][1], w01.x, ab1);
        FMA2(acc[1][1], w01.y, ab1);
        FMA2(acc[2][1], w23.x, ab1);
        FMA2(acc[3][1], w23.y, ab1);
    }
}

__global__ void __launch_bounds__(NTHR, 1)
eirnn_kernel(const float* __restrict__ hid,
             const float* __restrict__ win0,
             const float* __restrict__ win1,
             const float* __restrict__ win2,
             const float* __restrict__ wrec,
             const float* __restrict__ bg,
             float* __restrict__ out) {
    extern __shared__ float smem[];
    float* red = smem + REDO;
    const int tid = threadIdx.x;
    const int w = tid >> 5, lane = tid & 31;
    const int s = lane & 1, b2 = (lane >> 1) * 2;
    const int kb = 2 * w + s;
    const int ce = tid >> 6, be = tid & 63;
    const int c0 = blockIdx.x * 8, cge = c0 + ce;

    load_w(win0 + c0 * 512, 512, smem + WOFF0, 0, tid);
    load_w(wrec + 0 * 1048576 + c0 * 1024, 1024, smem + WOFF0 + 512 * 8, 1, tid);
    load_w(win1 + c0 * 1024, 1024, smem + WOFF1, 0, tid);
    load_w(wrec + 1 * 1048576 + c0 * 1024, 1024, smem + WOFF1 + 1024 * 8, 1, tid);
    load_w(win2 + c0 * 1024, 1024, smem + WOFF2, 0, tid);
    load_w(wrec + 2 * 1048576 + c0 * 1024, 1024, smem + WOFF2 + 1024 * 8, 1, tid);

    for (int idx = tid; idx < 8 * 64; idx += NTHR) {
        int i = idx >> 6, b = idx & 63;
        float hv = hid[b * 1024 + c0 + i];
#pragma unroll
        for (int l = 0; l < 3; l++) {
            g_h[0][l][(c0 + i) * 64 + b] = hv;
            out[AH_OFF + l * AH_L + b * 1024 + c0 + i] = hv;
        }
    }
    __threadfence();
    __syncthreads();
    if (tid == 0) atomicAdd(&g_init, 1);
    wait_ge(&g_init, NBLK);

    const float emask = (cge < NE) ? 1.f : 0.f;
    float bias_r[3];
#pragma unroll
    for (int l = 0; l < 3; l++) bias_r[l] = bg[l * 1024 + cge];
    float vr[3] = {0.f, 0.f, 0.f};
    const int wOff[3] = {WOFF0, WOFF1, WOFF2};
    const int mygrp = be >> 5;           // epilogue group of this thread
    const int u = be & 31;
    const int ue = u ^ ((u >> 2) & 3);

    int n = 0;
    for (int t = 0; t < 128; t++) {
        int tp = t & 1;
#pragma unroll 1
        for (int l = 0; l < 3; l++) {
            const float* wl = smem + wOff[l];
            const int Kf = l ? 1024 : 512;
#pragma unroll 1
            for (int g = 0; g < 2; g++) {
                const int goff = g * 32;
                unsigned long long acc[4][2];
#pragma unroll
                for (int i = 0; i < 4; i++) { acc[i][0] = 0ull; acc[i][1] = 0ull; }

                if (n >= 3) wait_ge(&g_cnt16[(((n - 3) & 7) << 1) | g], NBLK);
                accum<32>(acc, g_h[tp][l], wl + Kf * 8, kb, goff, b2);
                if (l > 0) {
                    wait_ge(&g_cnt16[(((n - 1) & 7) << 1) | g], NBLK);
                    accum<32>(acc, g_ci[tp][l - 1], wl, kb, goff, b2);
                } else {
                    accum<16>(acc, g_xT + t * 32768, wl, kb, goff, b2);
                }

                // combine s=0/1 within warp, even lanes write slice partials
#pragma unroll
                for (int cp = 0; cp < 4; cp++)
#pragma unroll
                    for (int b = 0; b < 2; b++) {
                        unsigned long long o = __shfl_xor_sync(0xffffffffu, acc[cp][b], 1);
                        ADD2(acc[cp][b], o);
                    }
                if (s == 0) {
#pragma unroll
                    for (int b = 0; b < 2; b++) {
                        int uu = b2 + b, up = uu ^ ((uu >> 2) & 3);
                        ulonglong2* dst = (ulonglong2*)(red + w * 256 + up * 8);
                        ulonglong2 v1, v2;
                        v1.x = acc[0][b]; v1.y = acc[1][b];
                        v2.x = acc[2][b]; v2.y = acc[3][b];
                        dst[0] = v1;
                        dst[1] = v2;
                    }
                }
                __syncthreads();

                if (mygrp == g) {
                    float sum = bias_r[l];
#pragma unroll
                    for (int q = 0; q < 16; q++) sum += red[q * 256 + ue * 8 + ce];
                    vr[l] = (1.f - ALPHA) * vr[l] + ALPHA * sum;
                    float h = fmaxf(vr[l], 0.f);
                    g_h[1 - tp][l][cge * 64 + be] = h;
                    smem[HBUF + u * 9 + ce] = h;
                    float ci = h * emask;
                    if (l < 2) g_ci[tp][l - 0 ? l : 0][cge * 64 + be] = ci;  // l<2 only
                    else       smem[OBUF + u * 9 + ce] = ci;
                }
                __threadfence();
                __syncthreads();

                if (tid < 256) {
                    int cw = tid & 7, bw = tid >> 3;   // bw 0..31
                    out[AH_OFF + l * AH_L + (t + 1) * BH + (goff + bw) * 1024 + c0 + cw] =
                        smem[HBUF + bw * 9 + cw];
                    if (l == 2)
                        out[t * BH + (goff + bw) * 1024 + c0 + cw] = smem[OBUF + bw * 9 + cw];
                }
                if (tid == 0) {
                    int r = atomicAdd(&g_cnt16[((n & 7) << 1) | g], 1);
                    if (r == NBLK - 1 && n >= 4)
                        atomicExch(&g_cnt16[(((n + 4) & 7) << 1) | g], 0);
                }
            }
            n++;
        }
    }
}

extern "C" void kernel_launch(void* const* d_in, const int* in_sizes, int n_in,
                              void* d_out, int out_size) {
    const float* x    = (const float*)d_in[0];
    const float* hid  = (const float*)d_in[1];
    const float* win0 = (const float*)d_in[2];
    const float* win1 = (const float*)d_in[3];
    const float* win2 = (const float*)d_in[4];
    const float* wrec = (const float*)d_in[5];
    const float* bg   = (const float*)d_in[6];
    float* out = (float*)d_out;

    cudaFuncSetAttribute(eirnn_kernel, cudaFuncAttributeMaxDynamicSharedMemorySize, SMEM_BYTES);
    xt_kernel<<<128 * 512 * 64 / 256, 256>>>(x);
    eirnn_kernel<<<NBLK, NTHR, SMEM_BYTES>>>(hid, win0, win1, win2, wrec, bg, out);
}

// round 15
// speedup vs baseline: 1.1808x; 1.1808x over previous
#include <cuda_runtime.h>
#include <math.h>

#define NBLK 256
#define NTHR 256
#define ALPHA 0.2f
#define NE 819

// SMEM float offsets: per-layer weights [k][4] (ff rows then Dale-signed rec rows)
#define WOFF0 0          // 1536*4
#define WOFF1 6144       // 2048*4
#define WOFF2 14336      // 2048*4
#define REDO  22528      // 8 x 64 x 4 reduction
#define HBUF  24576      // 64*5
#define OBUF  24896      // 64*5
#define SMEM_BYTES (25216 * 4)   // 100864

#define AH_OFF 8388608
#define AH_L   8454144
#define BH     65536

__device__ float g_xT[128 * 512 * 64];
__device__ float g_h[2][3][1024 * 64];
__device__ float g_ci[2][2][1024 * 64];
__device__ int g_cnt8[8];
__device__ int g_init;

__global__ void xt_kernel(const float* __restrict__ x) {
    int idx = blockIdx.x * 256 + threadIdx.x;
    int b = idx & 63, k = (idx >> 6) & 511, t = idx >> 15;
    g_xT[idx] = x[t * 32768 + b * 512 + k];
    if (idx < 8) g_cnt8[idx] = 0;
    if (idx == 8) g_init = 0;
}

__device__ __forceinline__ void wait_ge(const int* p, int val) {
    int v;
    do {
        asm volatile("ld.global.cg.b32 %0, [%1];" : "=r"(v) : "l"(p));
        if (v >= val) break;
        __nanosleep(64);
    } while (true);
    __threadfence();
}

// load one weight slice (4 rows) into SMEM as [k][4], abs + optional Dale sign
__device__ void load_w(const float* __restrict__ g, int K, float* dst, int dale, int tid) {
    for (int idx = tid; idx < 4 * K; idx += NTHR) {
        int i = idx / K, k = idx - i * K;
        float v = fabsf(g[i * K + k]);
        if (dale && k >= NE) v = -v;
        dst[k * 4 + i] = v;
    }
}

#define FMA2(A, W, X) asm("fma.rn.f32x2 %0, %1, %2, %0;" : "+l"(A) : "l"(W), "l"(X))
#define ADD2(A, B)    asm("add.rn.f32x2 %0, %0, %1;" : "+l"(A) : "l"(B))

// 4 cols x 4 batches per thread; this (warp,s) slice covers k = kb + 16*i.
// Depth-8 rotating prefetch buffer hides L2 latency.
// Weight row stride per slice step: 16 rows * 4 floats = 16 ulonglong2.
template <int N>
__device__ __forceinline__ void accum(unsigned long long acc[2][4],
                                      const float* __restrict__ act,
                                      const float* __restrict__ wsm,
                                      int kb, int b4) {
    const float4* ap = (const float4*)(act + kb * 64 + b4);
    const ulonglong2* wp = (const ulonglong2*)(wsm + kb * 4);
    float4 abuf[8];
#pragma unroll
    for (int j = 0; j < 8; j++) abuf[j] = __ldcg(ap + j * 256);
#pragma unroll
    for (int i = 0; i < N; i++) {
        float4 a = abuf[i & 7];
        if (i + 8 < N) abuf[i & 7] = __ldcg(ap + (i + 8) * 256);
        ulonglong2 w01 = wp[i * 16];    // 4 cols packed as 2 f32x2 pairs
        unsigned long long ab[4];
        asm("mov.b64 %0, {%1, %1};" : "=l"(ab[0]) : "f"(a.x));
        asm("mov.b64 %0, {%1, %1};" : "=l"(ab[1]) : "f"(a.y));
        asm("mov.b64 %0, {%1, %1};" : "=l"(ab[2]) : "f"(a.z));
        asm("mov.b64 %0, {%1, %1};" : "=l"(ab[3]) : "f"(a.w));
#pragma unroll
        for (int b = 0; b < 4; b++) {
            FMA2(acc[0][b], w01.x, ab[b]);
            FMA2(acc[1][b], w01.y, ab[b]);
        }
    }
}

__global__ void __launch_bounds__(NTHR, 2)
eirnn_kernel(const float* __restrict__ hid,
             const float* __restrict__ win0,
             const float* __restrict__ win1,
             const float* __restrict__ win2,
             const float* __restrict__ wrec,
             const float* __restrict__ bg,
             float* __restrict__ out) {
    extern __shared__ float smem[];
    float* red = smem + REDO;
    const int tid = threadIdx.x;
    const int w = tid >> 5, lane = tid & 31;
    const int s = lane & 1, b4 = (lane >> 1) * 4;
    const int kb = 2 * w + s;                 // 16 k-slices
    const int ce = tid >> 6, be = tid & 63;   // epilogue: (col, batch)
    const int c0 = blockIdx.x * 4, cge = c0 + ce;

    load_w(win0 + c0 * 512, 512, smem + WOFF0, 0, tid);
    load_w(wrec + 0 * 1048576 + c0 * 1024, 1024, smem + WOFF0 + 512 * 4, 1, tid);
    load_w(win1 + c0 * 1024, 1024, smem + WOFF1, 0, tid);
    load_w(wrec + 1 * 1048576 + c0 * 1024, 1024, smem + WOFF1 + 1024 * 4, 1, tid);
    load_w(win2 + c0 * 1024, 1024, smem + WOFF2, 0, tid);
    load_w(wrec + 2 * 1048576 + c0 * 1024, 1024, smem + WOFF2 + 1024 * 4, 1, tid);

    for (int idx = tid; idx < 4 * 64; idx += NTHR) {
        int i = idx >> 6, b = idx & 63;
        float hv = hid[b * 1024 + c0 + i];
#pragma unroll
        for (int l = 0; l < 3; l++) {
            g_h[0][l][(c0 + i) * 64 + b] = hv;
            out[AH_OFF + l * AH_L + b * 1024 + c0 + i] = hv;
        }
    }
    __threadfence();
    __syncthreads();
    if (tid == 0) atomicAdd(&g_init, 1);
    wait_ge(&g_init, NBLK);

    const float emask = (cge < NE) ? 1.f : 0.f;
    float bias_r[3];
#pragma unroll
    for (int l = 0; l < 3; l++) bias_r[l] = bg[l * 1024 + cge];
    float vr[3] = {0.f, 0.f, 0.f};
    const int wOff[3] = {WOFF0, WOFF1, WOFF2};
    const int ue = be ^ ((be >> 2) & 3);

    int n = 0;
    for (int t = 0; t < 128; t++) {
        int tp = t & 1;
#pragma unroll 1
        for (int l = 0; l < 3; l++) {
            const float* wl = smem + wOff[l];
            const int Kf = l ? 1024 : 512;
            unsigned long long acc[2][4];
#pragma unroll
            for (int i = 0; i < 2; i++)
#pragma unroll
                for (int b = 0; b < 4; b++) acc[i][b] = 0ull;

            if (n >= 3) wait_ge(&g_cnt8[(n - 3) & 7], NBLK);
            accum<64>(acc, g_h[tp][l], wl + Kf * 4, kb, b4);
            if (l > 0) {
                wait_ge(&g_cnt8[(n - 1) & 7], NBLK);
                accum<64>(acc, g_ci[tp][l - 1], wl, kb, b4);
            } else {
                accum<32>(acc, g_xT + t * 32768, wl, kb, b4);
            }

            // combine s=0/1 within warp, even lanes write slice partials
#pragma unroll
            for (int cp = 0; cp < 2; cp++)
#pragma unroll
                for (int b = 0; b < 4; b++) {
                    unsigned long long o = __shfl_xor_sync(0xffffffffu, acc[cp][b], 1);
                    ADD2(acc[cp][b], o);
                }
            if (s == 0) {
#pragma unroll
                for (int b = 0; b < 4; b++) {
                    int uu = b4 + b, up = uu ^ ((uu >> 2) & 3);
                    ulonglong2 v;
                    v.x = acc[0][b];
                    v.y = acc[1][b];
                    *(ulonglong2*)(red + w * 256 + up * 4) = v;
                }
            }
            __syncthreads();

            float sum = bias_r[l];
#pragma unroll
            for (int q = 0; q < 8; q++) sum += red[q * 256 + ue * 4 + ce];
            vr[l] = (1.f - ALPHA) * vr[l] + ALPHA * sum;
            float h = fmaxf(vr[l], 0.f);
            g_h[1 - tp][l][cge * 64 + be] = h;
            smem[HBUF + be * 5 + ce] = h;
            float ci = h * emask;
            if (l < 2) g_ci[tp][l][cge * 64 + be] = ci;
            else       smem[OBUF + be * 5 + ce] = ci;
            __threadfence();
            __syncthreads();

            int cw = tid & 3, bw = tid >> 2;
            out[AH_OFF + l * AH_L + (t + 1) * BH + bw * 1024 + c0 + cw] =
                smem[HBUF + bw * 5 + cw];
            if (l == 2)
                out[t * BH + bw * 1024 + c0 + cw] = smem[OBUF + bw * 5 + cw];
            if (tid == 0) {
                int r = atomicAdd(&g_cnt8[n & 7], 1);
                if (r == NBLK - 1 && n >= 4) atomicExch(&g_cnt8[(n + 4) & 7], 0);
            }
            n++;
        }
    }
}

extern "C" void kernel_launch(void* const* d_in, const int* in_sizes, int n_in,
                              void* d_out, int out_size) {
    const float* x    = (const float*)d_in[0];
    const float* hid  = (const float*)d_in[1];
    const float* win0 = (const float*)d_in[2];
    const float* win1 = (const float*)d_in[3];
    const float* win2 = (const float*)d_in[4];
    const float* wrec = (const float*)d_in[5];
    const float* bg   = (const float*)d_in[6];
    float* out = (float*)d_out;

    cudaFuncSetAttribute(eirnn_kernel, cudaFuncAttributeMaxDynamicSharedMemorySize, SMEM_BYTES);
    xt_kernel<<<128 * 512 * 64 / 256, 256>>>(x);
    eirnn_kernel<<<NBLK, NTHR, SMEM_BYTES>>>(hid, win0, win1, win2, wrec, bg, out);
}

// round 16
// speedup vs baseline: 1.4354x; 1.2156x over previous
#include <cuda_runtime.h>
#include <math.h>

#define NBLK 128
#define NTHR 512
#define ALPHA 0.2f
#define NE 819

// SMEM float offsets: per-layer weights [k][8] (ff rows then Dale-signed rec rows)
#define WOFF0 0          // 1536*8
#define WOFF1 12288      // 2048*8
#define WOFF2 28672      // 2048*8
#define REDO  45056      // 16 x 64 x 8 reduction
#define HBUF  53248      // 64*9
#define OBUF  53824      // 64*9
#define SMEM_BYTES (54400 * 4)

#define AH_OFF 8388608
#define AH_L   8454144
#define BH     65536

__device__ float g_xT[128 * 512 * 64];
__device__ float g_h[2][3][1024 * 64];
__device__ float g_ci[2][2][1024 * 64];
// Tree barrier: 8 rotating slots; per slot 8 group counters (16 CTAs each) + 1 root.
// Padded to 128B (32 ints) so each counter owns an L2 line.
__device__ int g_grp[8 * 8 * 32];
__device__ int g_root[8 * 32];
__device__ int g_init;

__global__ void xt_kernel(const float* __restrict__ x) {
    int idx = blockIdx.x * 256 + threadIdx.x;
    int b = idx & 63, k = (idx >> 6) & 511, t = idx >> 15;
    g_xT[idx] = x[t * 32768 + b * 512 + k];
    if (idx < 8 * 8 * 32) g_grp[idx] = 0;
    if (idx >= 4096 && idx < 4096 + 8 * 32) g_root[idx - 4096] = 0;
    if (idx == 8192) g_init = 0;
}

__device__ __forceinline__ void wait_ge(const int* p, int val) {
    int v;
    do {
        asm volatile("ld.global.cg.b32 %0, [%1];" : "=r"(v) : "l"(p));
        if (v >= val) break;
        __nanosleep(64);
    } while (true);
    __threadfence();
}

__device__ void load_w(const float* __restrict__ g, int K, float* dst, int dale, int tid) {
    for (int idx = tid; idx < 8 * K; idx += NTHR) {
        int i = idx / K, k = idx - i * K;
        float v = fabsf(g[i * K + k]);
        if (dale && k >= NE) v = -v;
        dst[k * 8 + i] = v;
    }
}

#define FMA2(A, W, X) asm("fma.rn.f32x2 %0, %1, %2, %0;" : "+l"(A) : "l"(W), "l"(X))
#define ADD2(A, B)    asm("add.rn.f32x2 %0, %0, %1;" : "+l"(A) : "l"(B))

// 8 cols x 4 batches per thread; this (warp,s) slice covers k = kb + 32*i.
__device__ __forceinline__ void accum(unsigned long long acc[4][4],
                                      const float* __restrict__ act,
                                      const float* __restrict__ wsm,
                                      int kb, int b4, int n) {
    const float4* ap = (const float4*)(act + kb * 64 + b4);
    const ulonglong2* wp = (const ulonglong2*)(wsm + kb * 8);
#pragma unroll 4
    for (int i = 0; i < n; i++) {
        float4 a = __ldcg(ap);
        ap += 512;
        ulonglong2 w01 = wp[0];
        ulonglong2 w23 = wp[1];
        wp += 64;
        unsigned long long ab[4];
        asm("mov.b64 %0, {%1, %1};" : "=l"(ab[0]) : "f"(a.x));
        asm("mov.b64 %0, {%1, %1};" : "=l"(ab[1]) : "f"(a.y));
        asm("mov.b64 %0, {%1, %1};" : "=l"(ab[2]) : "f"(a.z));
        asm("mov.b64 %0, {%1, %1};" : "=l"(ab[3]) : "f"(a.w));
#pragma unroll
        for (int b = 0; b < 4; b++) {
            FMA2(acc[0][b], w01.x, ab[b]);
            FMA2(acc[1][b], w01.y, ab[b]);
            FMA2(acc[2][b], w23.x, ab[b]);
            FMA2(acc[3][b], w23.y, ab[b]);
        }
    }
}

__global__ void __launch_bounds__(NTHR, 1)
eirnn_kernel(const float* __restrict__ hid,
             const float* __restrict__ win0,
             const float* __restrict__ win1,
             const float* __restrict__ win2,
             const float* __restrict__ wrec,
             const float* __restrict__ bg,
             float* __restrict__ out) {
    extern __shared__ float smem[];
    float* red = smem + REDO;
    const int tid = threadIdx.x;
    const int w = tid >> 5, lane = tid & 31;
    const int s = lane & 1, b4 = (lane >> 1) * 4;
    const int kb = 2 * w + s;
    const int ce = tid >> 6, be = tid & 63;
    const int c0 = blockIdx.x * 8, cge = c0 + ce;
    const int grp = blockIdx.x >> 4;      // 8 groups of 16 CTAs

    load_w(win0 + c0 * 512, 512, smem + WOFF0, 0, tid);
    load_w(wrec + 0 * 1048576 + c0 * 1024, 1024, smem + WOFF0 + 512 * 8, 1, tid);
    load_w(win1 + c0 * 1024, 1024, smem + WOFF1, 0, tid);
    load_w(wrec + 1 * 1048576 + c0 * 1024, 1024, smem + WOFF1 + 1024 * 8, 1, tid);
    load_w(win2 + c0 * 1024, 1024, smem + WOFF2, 0, tid);
    load_w(wrec + 2 * 1048576 + c0 * 1024, 1024, smem + WOFF2 + 1024 * 8, 1, tid);

    for (int idx = tid; idx < 8 * 64; idx += NTHR) {
        int i = idx >> 6, b = idx & 63;
        float hv = hid[b * 1024 + c0 + i];
#pragma unroll
        for (int l = 0; l < 3; l++) {
            g_h[0][l][(c0 + i) * 64 + b] = hv;
            out[AH_OFF + l * AH_L + b * 1024 + c0 + i] = hv;
        }
    }
    __threadfence();
    __syncthreads();
    if (tid == 0) atomicAdd(&g_init, 1);
    wait_ge(&g_init, NBLK);

    const float emask = (cge < NE) ? 1.f : 0.f;
    float bias_r[3];
#pragma unroll
    for (int l = 0; l < 3; l++) bias_r[l] = bg[l * 1024 + cge];
    float vr[3] = {0.f, 0.f, 0.f};
    const int wOff[3] = {WOFF0, WOFF1, WOFF2};

    int n = 0;
    for (int t = 0; t < 128; t++) {
        int tp = t & 1;
#pragma unroll 1
        for (int l = 0; l < 3; l++) {
            const float* wl = smem + wOff[l];
            const int Kf = l ? 1024 : 512;
            unsigned long long acc[4][4];
#pragma unroll
            for (int i = 0; i < 4; i++)
#pragma unroll
                for (int b = 0; b < 4; b++) acc[i][b] = 0ull;

            if (n >= 3) wait_ge(&g_root[((n - 3) & 7) * 32], 8);
            accum(acc, g_h[tp][l], wl + Kf * 8, kb, b4, 32);
            if (l > 0) {
                wait_ge(&g_root[((n - 1) & 7) * 32], 8);
                accum(acc, g_ci[tp][l - 1], wl, kb, b4, 32);
            } else {
                accum(acc, g_xT + t * 32768, wl, kb, b4, 16);
            }

            // combine s=0/1 within warp, even lanes write slice partials
#pragma unroll
            for (int cp = 0; cp < 4; cp++)
#pragma unroll
                for (int b = 0; b < 4; b++) {
                    unsigned long long o = __shfl_xor_sync(0xffffffffu, acc[cp][b], 1);
                    ADD2(acc[cp][b], o);
                }
            if (s == 0) {
#pragma unroll
                for (int b = 0; b < 4; b++) {
                    int uu = b4 + b, up = uu ^ ((uu >> 2) & 3);
                    ulonglong2* dst = (ulonglong2*)(red + w * 512 + up * 8);
                    ulonglong2 v1, v2;
                    v1.x = acc[0][b]; v1.y = acc[1][b];
                    v2.x = acc[2][b]; v2.y = acc[3][b];
                    dst[0] = v1;
                    dst[1] = v2;
                }
            }
            __syncthreads();

            const int ue = be ^ ((be >> 2) & 3);
            float sum = bias_r[l];
#pragma unroll
            for (int q = 0; q < 16; q++) sum += red[q * 512 + ue * 8 + ce];
            vr[l] = (1.f - ALPHA) * vr[l] + ALPHA * sum;
            float h = fmaxf(vr[l], 0.f);
            g_h[1 - tp][l][cge * 64 + be] = h;
            smem[HBUF + be * 9 + ce] = h;
            float ci = h * emask;
            if (l < 2) g_ci[tp][l][cge * 64 + be] = ci;
            else       smem[OBUF + be * 9 + ce] = ci;
            __threadfence();
            __syncthreads();

            int cw = tid & 7, bw = tid >> 3;
            out[AH_OFF + l * AH_L + (t + 1) * BH + bw * 1024 + c0 + cw] =
                smem[HBUF + bw * 9 + cw];
            if (l == 2)
                out[t * BH + bw * 1024 + c0 + cw] = smem[OBUF + bw * 9 + cw];

            // hierarchical arrive: group (16-way) then root (8-way)
            if (tid == 0) {
                int r = atomicAdd(&g_grp[(((n & 7) << 3) | grp) * 32], 1);
                if (r == 15) {
                    int q = atomicAdd(&g_root[(n & 7) * 32], 1);
                    if (q == 7 && n >= 4) {
                        int s4 = (n + 4) & 7;
#pragma unroll
                        for (int g2 = 0; g2 < 8; g2++)
                            atomicExch(&g_grp[((s4 << 3) | g2) * 32], 0);
                        atomicExch(&g_root[s4 * 32], 0);
                    }
                }
            }
            n++;
        }
    }
}

extern "C" void kernel_launch(void* const* d_in, const int* in_sizes, int n_in,
                              void* d_out, int out_size) {
    const float* x    = (const float*)d_in[0];
    const float* hid  = (const float*)d_in[1];
    const float* win0 = (const float*)d_in[2];
    const float* win1 = (const float*)d_in[3];
    const float* win2 = (const float*)d_in[4];
    const float* wrec = (const float*)d_in[5];
    const float* bg   = (const float*)d_in[6];
    float* out = (float*)d_out;

    cudaFuncSetAttribute(eirnn_kernel, cudaFuncAttributeMaxDynamicSharedMemorySize, SMEM_BYTES);
    xt_kernel<<<128 * 512 * 64 / 256, 256>>>(x);
    eirnn_kernel<<<NBLK, NTHR, SMEM_BYTES>>>(hid, win0, win1, win2, wrec, bg, out);
}